// round 1
// baseline (speedup 1.0000x reference)
#include <cuda_runtime.h>

// GCN forward: 4x (GEMM + CSR-gather aggregate) + pool + MLP head.
// All fp32. CSR built on-device each launch (graph-capturable, no allocs).

#define DD 128
#define NMAX 50000
#define EMAX 800000
#define GMAX 512

// ---------------- scratch (static device globals; no allocation) ----------------
__device__ int   g_is64;
__device__ float g_h[NMAX * DD];      // layer activation
__device__ float g_hw[NMAX * DD];     // h @ W
__device__ float g_dinv[NMAX];
__device__ float g_self[NMAX];
__device__ int   g_hist[NMAX];
__device__ int   g_rowstart[NMAX + 1];
__device__ int   g_cursor[NMAX];
__device__ int   g_csrc[EMAX];
__device__ float g_cw[EMAX];
__device__ float g_pool[GMAX * DD];
__device__ float g_m1[GMAX * DD];
__device__ float g_m2[GMAX * 64];

// ---------------- helpers ----------------
__device__ __forceinline__ long long idx_at(const void* p, long long i) {
    if (g_is64) return ((const long long*)p)[i];
    return (long long)((const int*)p)[i];
}

// Detect int64 vs int32 index buffers: for non-negative int64 values the odd
// 32-bit words (high halves) are all zero; for int32 random indices they are not.
__global__ void detect_kernel(const unsigned int* __restrict__ p) {
    if (threadIdx.x == 0 && blockIdx.x == 0) {
        int is64 = 1;
        for (int k = 1; k <= 15; k += 2)
            if (p[k] != 0u) { is64 = 0; break; }
        g_is64 = is64;
    }
}

__global__ void zero_hist_kernel(int n) {
    int i = blockIdx.x * blockDim.x + threadIdx.x;
    if (i < n) g_hist[i] = 0;
}

__global__ void hist_kernel(const void* __restrict__ ei, int E) {
    int e = blockIdx.x * blockDim.x + threadIdx.x;
    if (e < E) {
        int c = (int)idx_at(ei, (long long)E + e);
        atomicAdd(&g_hist[c], 1);
    }
}

__global__ void dinv_kernel(int n) {
    int i = blockIdx.x * blockDim.x + threadIdx.x;
    if (i < n) {
        float deg = (float)g_hist[i] + 1.0f;
        g_dinv[i] = rsqrtf(deg);
        g_self[i] = 1.0f / deg;
    }
}

// single-block exclusive scan of g_hist -> g_rowstart / g_cursor
__global__ void scan_kernel(int n, int E) {
    __shared__ int sums[1024];
    int t = threadIdx.x;
    int chunk = (n + 1023) / 1024;
    int b0 = t * chunk;
    int b1 = min(b0 + chunk, n);
    int s = 0;
    for (int i = b0; i < b1; i++) s += g_hist[i];
    sums[t] = s;
    __syncthreads();
    // Hillis-Steele inclusive scan
    for (int off = 1; off < 1024; off <<= 1) {
        int v = (t >= off) ? sums[t - off] : 0;
        __syncthreads();
        sums[t] += v;
        __syncthreads();
    }
    int run = (t == 0) ? 0 : sums[t - 1];
    for (int i = b0; i < b1; i++) {
        g_rowstart[i] = run;
        g_cursor[i] = run;
        run += g_hist[i];
    }
    if (t == 0) g_rowstart[n] = E;
}

__global__ void fill_kernel(const void* __restrict__ ei, int E) {
    int e = blockIdx.x * blockDim.x + threadIdx.x;
    if (e < E) {
        int r = (int)idx_at(ei, e);
        int c = (int)idx_at(ei, (long long)E + e);
        int pos = atomicAdd(&g_cursor[c], 1);
        g_csrc[pos] = r;
        g_cw[pos] = g_dinv[r] * g_dinv[c];
    }
}

// ---------------- GEMM: C[M,128] = A[M,128] @ W[128,128] ----------------
// block = 256 threads computes 64 rows x 128 cols; K tiled by 32.
__global__ void gemm_kernel(const float* __restrict__ A, const float* __restrict__ W,
                            float* __restrict__ C, int M) {
    __shared__ float As[32][68];   // transposed: As[k][m], padded stride 68 (16B aligned)
    __shared__ float Bs[32][128];
    int tid = threadIdx.x;
    int tx = tid & 15;             // 8 cols each
    int ty = tid >> 4;             // 4 rows each
    int row0 = blockIdx.x * 64;

    float acc[4][8];
#pragma unroll
    for (int r = 0; r < 4; r++)
#pragma unroll
        for (int c = 0; c < 8; c++) acc[r][c] = 0.0f;

    for (int k0 = 0; k0 < 128; k0 += 32) {
        // load A tile (64x32) transposed into As[k][m]
#pragma unroll
        for (int i = 0; i < 2; i++) {
            int f = tid + 256 * i;       // 0..511 float4 slots
            int r = f >> 3;              // 0..63
            int c4 = f & 7;              // 0..7
            float4 v = make_float4(0.f, 0.f, 0.f, 0.f);
            if (row0 + r < M)
                v = *(const float4*)&A[(long long)(row0 + r) * DD + k0 + c4 * 4];
            As[c4 * 4 + 0][r] = v.x;
            As[c4 * 4 + 1][r] = v.y;
            As[c4 * 4 + 2][r] = v.z;
            As[c4 * 4 + 3][r] = v.w;
        }
        // load B tile (32x128)
#pragma unroll
        for (int i = 0; i < 4; i++) {
            int f = tid + 256 * i;       // 0..1023 float4 slots
            int r = f >> 5;
            int c4 = f & 31;
            *(float4*)&Bs[r][c4 * 4] = *(const float4*)&W[(k0 + r) * DD + c4 * 4];
        }
        __syncthreads();
#pragma unroll
        for (int kk = 0; kk < 32; kk++) {
            float4 a4 = *(const float4*)&As[kk][ty * 4];
            float a[4] = {a4.x, a4.y, a4.z, a4.w};
            float4 b0 = *(const float4*)&Bs[kk][tx * 8];
            float4 b1 = *(const float4*)&Bs[kk][tx * 8 + 4];
            float b[8] = {b0.x, b0.y, b0.z, b0.w, b1.x, b1.y, b1.z, b1.w};
#pragma unroll
            for (int r = 0; r < 4; r++)
#pragma unroll
                for (int c = 0; c < 8; c++)
                    acc[r][c] = fmaf(a[r], b[c], acc[r][c]);
        }
        __syncthreads();
    }
#pragma unroll
    for (int r = 0; r < 4; r++) {
        int row = row0 + ty * 4 + r;
        if (row < M) {
            float4 o0 = make_float4(acc[r][0], acc[r][1], acc[r][2], acc[r][3]);
            float4 o1 = make_float4(acc[r][4], acc[r][5], acc[r][6], acc[r][7]);
            *(float4*)&C[(long long)row * DD + tx * 8] = o0;
            *(float4*)&C[(long long)row * DD + tx * 8 + 4] = o1;
        }
    }
}

// ---------------- gather aggregation (no atomics) ----------------
// one warp per node; lane handles 4 consecutive features (float4).
// h_out[i] = relu(b + self[i]*hw[i] + sum_e w_e * hw[src_e])
__global__ void gather_kernel(const float* __restrict__ hw, const float* __restrict__ bias,
                              float* __restrict__ hout, int N) {
    int gwarp = (blockIdx.x * blockDim.x + threadIdx.x) >> 5;
    int lane = threadIdx.x & 31;
    if (gwarp >= N) return;
    const float4* hw4 = (const float4*)hw;
    int s = g_rowstart[gwarp];
    int e = g_rowstart[gwarp + 1];
    float sf = g_self[gwarp];
    float4 v = hw4[(long long)gwarp * 32 + lane];
    float4 acc = make_float4(sf * v.x, sf * v.y, sf * v.z, sf * v.w);
    for (int j = s; j < e; j++) {
        int src = g_csrc[j];
        float w = g_cw[j];
        float4 u = hw4[(long long)src * 32 + lane];
        acc.x = fmaf(w, u.x, acc.x);
        acc.y = fmaf(w, u.y, acc.y);
        acc.z = fmaf(w, u.z, acc.z);
        acc.w = fmaf(w, u.w, acc.w);
    }
    float4 b = *(const float4*)&bias[lane * 4];
    acc.x = fmaxf(acc.x + b.x, 0.0f);
    acc.y = fmaxf(acc.y + b.y, 0.0f);
    acc.z = fmaxf(acc.z + b.z, 0.0f);
    acc.w = fmaxf(acc.w + b.w, 0.0f);
    ((float4*)hout)[(long long)gwarp * 32 + lane] = acc;
}

// ---------------- pooling ----------------
__global__ void zero_pool_kernel(int n) {
    int i = blockIdx.x * blockDim.x + threadIdx.x;
    if (i < n) g_pool[i] = 0.0f;
}

__global__ void pool_kernel(const void* __restrict__ batch, int N) {
    int t = blockIdx.x * blockDim.x + threadIdx.x;
    int node = t >> 5;
    int lane = t & 31;
    if (node >= N) return;
    int gb = (int)idx_at(batch, node);
    float4 v = ((const float4*)g_h)[(long long)node * 32 + lane];
    float* base = &g_pool[gb * DD + lane * 4];
    atomicAdd(base + 0, v.x);
    atomicAdd(base + 1, v.y);
    atomicAdd(base + 2, v.z);
    atomicAdd(base + 3, v.w);
}

// ---------------- MLP (one block per output row) ----------------
__global__ void mlp_kernel(const float* __restrict__ A, const float* __restrict__ W,
                           const float* __restrict__ b, float* __restrict__ out,
                           int K, int Nn, int do_relu) {
    __shared__ float arow[DD];
    int i = blockIdx.x;
    for (int k = threadIdx.x; k < K; k += blockDim.x) arow[k] = A[i * K + k];
    __syncthreads();
    int j = threadIdx.x;
    if (j < Nn) {
        float s = b[j];
        for (int k = 0; k < K; k++) s = fmaf(arow[k], W[k * Nn + j], s);
        if (do_relu) s = fmaxf(s, 0.0f);
        out[i * Nn + j] = s;
    }
}

// ---------------- launch ----------------
extern "C" void kernel_launch(void* const* d_in, const int* in_sizes, int n_in,
                              void* d_out, int out_size) {
    const float* x      = (const float*)d_in[0];
    const void*  ei     = d_in[1];
    const void*  batch  = d_in[2];
    const float* W_conv = (const float*)d_in[3];
    const float* b_conv = (const float*)d_in[4];
    const float* W1 = (const float*)d_in[5];
    const float* b1 = (const float*)d_in[6];
    const float* W2 = (const float*)d_in[7];
    const float* b2 = (const float*)d_in[8];
    const float* W3 = (const float*)d_in[9];
    const float* b3 = (const float*)d_in[10];

    int N = in_sizes[0] / DD;           // 50000
    int E = in_sizes[1] / 2;            // 800000
    int n_layers = in_sizes[3] / (DD * DD);  // 4
    int G = out_size / 10;              // 512

    // preprocessing: dtype detect, degree, CSR
    detect_kernel<<<1, 32>>>((const unsigned int*)ei);
    zero_hist_kernel<<<(N + 255) / 256, 256>>>(N);
    hist_kernel<<<(E + 255) / 256, 256>>>(ei, E);
    dinv_kernel<<<(N + 255) / 256, 256>>>(N);
    scan_kernel<<<1, 1024>>>(N, E);
    fill_kernel<<<(E + 255) / 256, 256>>>(ei, E);

    // resolve device symbol addresses (host side, capture-safe: no sync needed
    // because cudaGetSymbolAddress is not a stream op)
    static float* p_h = nullptr;
    static float* p_hw = nullptr;
    if (!p_h) {
        cudaGetSymbolAddress((void**)&p_h, g_h);
        cudaGetSymbolAddress((void**)&p_hw, g_hw);
    }
    static float* p_pool = nullptr;
    static float* p_m1 = nullptr;
    static float* p_m2 = nullptr;
    if (!p_pool) {
        cudaGetSymbolAddress((void**)&p_pool, g_pool);
        cudaGetSymbolAddress((void**)&p_m1, g_m1);
        cudaGetSymbolAddress((void**)&p_m2, g_m2);
    }

    int gemm_grid = (N + 63) / 64;
    int gather_grid = (N + 7) / 8;        // 8 warps/block
    for (int l = 0; l < n_layers; l++) {
        const float* hin = (l == 0) ? x : p_h;
        gemm_kernel<<<gemm_grid, 256>>>(hin, W_conv + (long long)l * DD * DD, p_hw, N);
        gather_kernel<<<gather_grid, 256>>>(p_hw, b_conv + l * DD, p_h, N);
    }

    zero_pool_kernel<<<(G * DD + 255) / 256, 256>>>(G * DD);
    pool_kernel<<<(N * 32 + 255) / 256, 256>>>(batch, N);

    mlp_kernel<<<G, 128>>>(p_pool, W1, b1, p_m1, DD, DD, 1);
    mlp_kernel<<<G, 128>>>(p_m1, W2, b2, p_m2, DD, 64, 1);
    mlp_kernel<<<G, 64>>>(p_m2, W3, b3, (float*)d_out, 64, 10, 0);
}

// round 3
// speedup vs baseline: 1.5219x; 1.5219x over previous
#include <cuda_runtime.h>
#include <cuda_bf16.h>
#include <cstdint>

// GCN forward: 4x (mma.sync bf16x3 GEMM + CSR-gather) + pool + MLP head.
// tcgen05 is unavailable (harness compiles base sm_103 PTX), so GEMM uses
// warp-level mma.sync m16n8k16 bf16 with a 3-term hi/lo split for fp32-like accuracy.

#define DD 128
#define NMAX 50000
#define EMAX 800000
#define GMAX 512

// ---------------- scratch (static device globals; no allocation) ----------------
__device__ int   g_is64;
__device__ float g_h[NMAX * DD];
__device__ float g_hw[NMAX * DD];
__device__ float g_dinv[NMAX];
__device__ float g_self[NMAX];
__device__ int   g_hist[NMAX];
__device__ int   g_rowstart[NMAX + 1];
__device__ int   g_cursor[NMAX];
__device__ int   g_csrc[EMAX];
__device__ float g_cw[EMAX];
__device__ float g_pool[GMAX * DD];
__device__ float g_m1[GMAX * DD];
__device__ float g_m2[GMAX * 64];
// Pre-split, transposed weights: [layer][plane hi/lo][n*128 + k] bf16
__device__ __nv_bfloat16 g_Wbf[4][2][DD * DD];

// ---------------- helpers ----------------
__device__ __forceinline__ uint32_t smem_u32(const void* p) {
    return (uint32_t)__cvta_generic_to_shared(p);
}
__device__ __forceinline__ long long idx_at(const void* p, long long i) {
    if (g_is64) return ((const long long*)p)[i];
    return (long long)((const int*)p)[i];
}

__global__ void detect_kernel(const unsigned int* __restrict__ p) {
    if (threadIdx.x == 0 && blockIdx.x == 0) {
        int is64 = 1;
        for (int k = 1; k <= 15; k += 2)
            if (p[k] != 0u) { is64 = 0; break; }
        g_is64 = is64;
    }
}

__global__ void zero_hist_kernel(int n) {
    int i = blockIdx.x * blockDim.x + threadIdx.x;
    if (i < n) g_hist[i] = 0;
}

__global__ void hist_kernel(const void* __restrict__ ei, int E) {
    int e = blockIdx.x * blockDim.x + threadIdx.x;
    if (e < E) {
        int c = (int)idx_at(ei, (long long)E + e);
        atomicAdd(&g_hist[c], 1);
    }
}

__global__ void dinv_kernel(int n) {
    int i = blockIdx.x * blockDim.x + threadIdx.x;
    if (i < n) {
        float deg = (float)g_hist[i] + 1.0f;
        g_dinv[i] = rsqrtf(deg);
        g_self[i] = 1.0f / deg;
    }
}

__global__ void scan_kernel(int n, int E) {
    __shared__ int sums[1024];
    int t = threadIdx.x;
    int chunk = (n + 1023) / 1024;
    int b0 = t * chunk;
    int b1 = min(b0 + chunk, n);
    int s = 0;
    for (int i = b0; i < b1; i++) s += g_hist[i];
    sums[t] = s;
    __syncthreads();
    for (int off = 1; off < 1024; off <<= 1) {
        int v = (t >= off) ? sums[t - off] : 0;
        __syncthreads();
        sums[t] += v;
        __syncthreads();
    }
    int run = (t == 0) ? 0 : sums[t - 1];
    for (int i = b0; i < b1; i++) {
        g_rowstart[i] = run;
        g_cursor[i] = run;
        run += g_hist[i];
    }
    if (t == 0) g_rowstart[n] = E;
}

__global__ void fill_kernel(const void* __restrict__ ei, int E) {
    int e = blockIdx.x * blockDim.x + threadIdx.x;
    if (e < E) {
        int r = (int)idx_at(ei, e);
        int c = (int)idx_at(ei, (long long)E + e);
        int pos = atomicAdd(&g_cursor[c], 1);
        g_csrc[pos] = r;
        g_cw[pos] = g_dinv[r] * g_dinv[c];
    }
}

// ---------------- weight prep: transpose + bf16 hi/lo split ----------------
__global__ void prep_w_kernel(const float* __restrict__ W_conv, int n_layers) {
    int idx = blockIdx.x * blockDim.x + threadIdx.x;
    int total = n_layers * DD * DD;
    if (idx >= total) return;
    int l = idx / (DD * DD);
    int rem = idx % (DD * DD);
    int k = rem / DD;
    int n = rem % DD;
    float w = W_conv[(long long)l * DD * DD + k * DD + n];
    __nv_bfloat16 hi = __float2bfloat16(w);
    __nv_bfloat16 lo = __float2bfloat16(w - __bfloat162float(hi));
    g_Wbf[l][0][n * DD + k] = hi;
    g_Wbf[l][1][n * DD + k] = lo;
}

// ---------------- mma.sync bf16x3 GEMM: C[M,128] = A[M,128] @ W ----------------
// CTA: 256 thr, tile 128x128, K=128 fully resident. Warp tile 32(M)x64(N).
#define ASTR 136                      // bf16 elements per smem row (conflict-free ldmatrix)
#define TILE_BYTES (128 * ASTR * 2)   // 34816
#define SM_AH 0
#define SM_AL (TILE_BYTES)
#define SM_BH (2 * TILE_BYTES)
#define SM_BL (3 * TILE_BYTES)
#define SM_TOTAL (4 * TILE_BYTES)     // 139264

__device__ __forceinline__ void ldmat_x4(uint32_t* r, uint32_t addr) {
    asm volatile("ldmatrix.sync.aligned.m8n8.x4.shared.b16 {%0,%1,%2,%3}, [%4];"
                 : "=r"(r[0]), "=r"(r[1]), "=r"(r[2]), "=r"(r[3]) : "r"(addr));
}
__device__ __forceinline__ void ldmat_x2(uint32_t* r, uint32_t addr) {
    asm volatile("ldmatrix.sync.aligned.m8n8.x2.shared.b16 {%0,%1}, [%2];"
                 : "=r"(r[0]), "=r"(r[1]) : "r"(addr));
}
__device__ __forceinline__ void mma_bf16(float* c, const uint32_t* a, const uint32_t* b) {
    asm volatile("mma.sync.aligned.m16n8k16.row.col.f32.bf16.bf16.f32 "
                 "{%0,%1,%2,%3}, {%4,%5,%6,%7}, {%8,%9}, {%0,%1,%2,%3};"
                 : "+f"(c[0]), "+f"(c[1]), "+f"(c[2]), "+f"(c[3])
                 : "r"(a[0]), "r"(a[1]), "r"(a[2]), "r"(a[3]), "r"(b[0]), "r"(b[1]));
}

__global__ void __launch_bounds__(256, 1)
gemm_mma_kernel(const float* __restrict__ A,
                const __nv_bfloat16* __restrict__ Whi,
                const __nv_bfloat16* __restrict__ Wlo,
                float* __restrict__ C, int M) {
    extern __shared__ char smem[];
    __nv_bfloat16* sAh = (__nv_bfloat16*)(smem + SM_AH);
    __nv_bfloat16* sAl = (__nv_bfloat16*)(smem + SM_AL);
    __nv_bfloat16* sBh = (__nv_bfloat16*)(smem + SM_BH);
    __nv_bfloat16* sBl = (__nv_bfloat16*)(smem + SM_BL);

    int tid = threadIdx.x;
    int lane = tid & 31;
    int wid = tid >> 5;
    int wm = wid & 3;        // 0..3 along M (32 rows each)
    int wn = wid >> 2;       // 0..1 along N (64 cols each)
    int row0 = blockIdx.x * 128;

    // ---- load + split A tile (128x128 fp32 -> bf16 hi/lo) ----
#pragma unroll
    for (int i = 0; i < 16; i++) {
        int f = tid + 256 * i;          // 0..4095 float4 slots
        int row = f >> 5;
        int c4 = f & 31;
        float4 v = make_float4(0.f, 0.f, 0.f, 0.f);
        if (row0 + row < M)
            v = *(const float4*)&A[(long long)(row0 + row) * DD + c4 * 4];
        __nv_bfloat16 h0 = __float2bfloat16(v.x), l0 = __float2bfloat16(v.x - __bfloat162float(h0));
        __nv_bfloat16 h1 = __float2bfloat16(v.y), l1 = __float2bfloat16(v.y - __bfloat162float(h1));
        __nv_bfloat16 h2 = __float2bfloat16(v.z), l2 = __float2bfloat16(v.z - __bfloat162float(h2));
        __nv_bfloat16 h3 = __float2bfloat16(v.w), l3 = __float2bfloat16(v.w - __bfloat162float(h3));
        __nv_bfloat162* ph = (__nv_bfloat162*)&sAh[row * ASTR + c4 * 4];
        __nv_bfloat162* pl = (__nv_bfloat162*)&sAl[row * ASTR + c4 * 4];
        ph[0] = __nv_bfloat162(h0, h1); ph[1] = __nv_bfloat162(h2, h3);
        pl[0] = __nv_bfloat162(l0, l1); pl[1] = __nv_bfloat162(l2, l3);
    }
    // ---- copy B tiles (pre-split bf16, [n][k]) ----
#pragma unroll
    for (int i = 0; i < 8; i++) {
        int f = tid + 256 * i;          // 0..2047 uint4 slots (8 bf16 each)
        int row = f >> 4;
        int u4 = f & 15;
        *(uint4*)&sBh[row * ASTR + u4 * 8] = *(const uint4*)&Whi[row * DD + u4 * 8];
        *(uint4*)&sBl[row * ASTR + u4 * 8] = *(const uint4*)&Wlo[row * DD + u4 * 8];
    }
    __syncthreads();

    float acc[2][8][4];
#pragma unroll
    for (int ma = 0; ma < 2; ma++)
#pragma unroll
        for (int na = 0; na < 8; na++)
#pragma unroll
            for (int q = 0; q < 4; q++) acc[ma][na][q] = 0.0f;

    int arow = wm * 32 + (lane & 15);
    int acol_half = (lane >> 4) * 8;        // 0 or 8
    int brow = wn * 64 + (lane & 7);
    int bcol_half = ((lane >> 3) & 1) * 8;  // 0 or 8

    for (int k0 = 0; k0 < 128; k0 += 16) {
        uint32_t ah[2][4], al[2][4];
#pragma unroll
        for (int ma = 0; ma < 2; ma++) {
            uint32_t off = (uint32_t)((arow + ma * 16) * ASTR + k0 + acol_half) * 2;
            ldmat_x4(ah[ma], smem_u32(smem + SM_AH) + off);
            ldmat_x4(al[ma], smem_u32(smem + SM_AL) + off);
        }
        uint32_t bh[8][2], bl[8][2];
#pragma unroll
        for (int na = 0; na < 8; na++) {
            uint32_t off = (uint32_t)((brow + na * 8) * ASTR + k0 + bcol_half) * 2;
            ldmat_x2(bh[na], smem_u32(smem + SM_BH) + off);
            ldmat_x2(bl[na], smem_u32(smem + SM_BL) + off);
        }
#pragma unroll
        for (int ma = 0; ma < 2; ma++)
#pragma unroll
            for (int na = 0; na < 8; na++) {
                mma_bf16(acc[ma][na], ah[ma], bh[na]);
                mma_bf16(acc[ma][na], ah[ma], bl[na]);
                mma_bf16(acc[ma][na], al[ma], bh[na]);
            }
    }

    // ---- epilogue: fragment -> global ----
    int gr = lane >> 2;
    int tg = lane & 3;
#pragma unroll
    for (int ma = 0; ma < 2; ma++) {
        int r0 = row0 + wm * 32 + ma * 16 + gr;
        int r1 = r0 + 8;
#pragma unroll
        for (int na = 0; na < 8; na++) {
            int col = wn * 64 + na * 8 + tg * 2;
            if (r0 < M)
                *(float2*)&C[(long long)r0 * DD + col] = make_float2(acc[ma][na][0], acc[ma][na][1]);
            if (r1 < M)
                *(float2*)&C[(long long)r1 * DD + col] = make_float2(acc[ma][na][2], acc[ma][na][3]);
        }
    }
}

// ---------------- gather aggregation (no atomics) ----------------
__global__ void gather_kernel(const float* __restrict__ hw, const float* __restrict__ bias,
                              float* __restrict__ hout, int N) {
    int gwarp = (blockIdx.x * blockDim.x + threadIdx.x) >> 5;
    int lane = threadIdx.x & 31;
    if (gwarp >= N) return;
    const float4* hw4 = (const float4*)hw;
    int s = g_rowstart[gwarp];
    int e = g_rowstart[gwarp + 1];
    float sf = g_self[gwarp];
    float4 v = hw4[(long long)gwarp * 32 + lane];
    float4 acc = make_float4(sf * v.x, sf * v.y, sf * v.z, sf * v.w);
    for (int j = s; j < e; j++) {
        int src = g_csrc[j];
        float w = g_cw[j];
        float4 u = hw4[(long long)src * 32 + lane];
        acc.x = fmaf(w, u.x, acc.x);
        acc.y = fmaf(w, u.y, acc.y);
        acc.z = fmaf(w, u.z, acc.z);
        acc.w = fmaf(w, u.w, acc.w);
    }
    float4 b = *(const float4*)&bias[lane * 4];
    acc.x = fmaxf(acc.x + b.x, 0.0f);
    acc.y = fmaxf(acc.y + b.y, 0.0f);
    acc.z = fmaxf(acc.z + b.z, 0.0f);
    acc.w = fmaxf(acc.w + b.w, 0.0f);
    ((float4*)hout)[(long long)gwarp * 32 + lane] = acc;
}

// ---------------- pooling ----------------
__global__ void zero_pool_kernel(int n) {
    int i = blockIdx.x * blockDim.x + threadIdx.x;
    if (i < n) g_pool[i] = 0.0f;
}

__global__ void pool_kernel(const void* __restrict__ batch, int N) {
    int t = blockIdx.x * blockDim.x + threadIdx.x;
    int node = t >> 5;
    int lane = t & 31;
    if (node >= N) return;
    int gb = (int)idx_at(batch, node);
    float4 v = ((const float4*)g_h)[(long long)node * 32 + lane];
    float* base = &g_pool[gb * DD + lane * 4];
    atomicAdd(base + 0, v.x);
    atomicAdd(base + 1, v.y);
    atomicAdd(base + 2, v.z);
    atomicAdd(base + 3, v.w);
}

// ---------------- MLP ----------------
__global__ void mlp_kernel(const float* __restrict__ A, const float* __restrict__ W,
                           const float* __restrict__ b, float* __restrict__ out,
                           int K, int Nn, int do_relu) {
    __shared__ float arow[DD];
    int i = blockIdx.x;
    for (int k = threadIdx.x; k < K; k += blockDim.x) arow[k] = A[i * K + k];
    __syncthreads();
    int j = threadIdx.x;
    if (j < Nn) {
        float s = b[j];
        for (int k = 0; k < K; k++) s = fmaf(arow[k], W[k * Nn + j], s);
        if (do_relu) s = fmaxf(s, 0.0f);
        out[i * Nn + j] = s;
    }
}

// ---------------- launch ----------------
extern "C" void kernel_launch(void* const* d_in, const int* in_sizes, int n_in,
                              void* d_out, int out_size) {
    const float* x      = (const float*)d_in[0];
    const void*  ei     = d_in[1];
    const void*  batch  = d_in[2];
    const float* W_conv = (const float*)d_in[3];
    const float* b_conv = (const float*)d_in[4];
    const float* W1 = (const float*)d_in[5];
    const float* b1 = (const float*)d_in[6];
    const float* W2 = (const float*)d_in[7];
    const float* b2 = (const float*)d_in[8];
    const float* W3 = (const float*)d_in[9];
    const float* b3 = (const float*)d_in[10];

    int N = in_sizes[0] / DD;
    int E = in_sizes[1] / 2;
    int n_layers = in_sizes[3] / (DD * DD);
    int G = out_size / 10;

    static bool attr_done = false;
    if (!attr_done) {
        cudaFuncSetAttribute(gemm_mma_kernel, cudaFuncAttributeMaxDynamicSharedMemorySize, SM_TOTAL);
        attr_done = true;
    }

    detect_kernel<<<1, 32>>>((const unsigned int*)ei);
    zero_hist_kernel<<<(N + 255) / 256, 256>>>(N);
    hist_kernel<<<(E + 255) / 256, 256>>>(ei, E);
    dinv_kernel<<<(N + 255) / 256, 256>>>(N);
    scan_kernel<<<1, 1024>>>(N, E);
    fill_kernel<<<(E + 255) / 256, 256>>>(ei, E);
    prep_w_kernel<<<(n_layers * DD * DD + 255) / 256, 256>>>(W_conv, n_layers);

    static float* p_h = nullptr;
    static float* p_hw = nullptr;
    static __nv_bfloat16* p_wbf = nullptr;
    static float* p_pool = nullptr;
    static float* p_m1 = nullptr;
    static float* p_m2 = nullptr;
    if (!p_h) {
        cudaGetSymbolAddress((void**)&p_h, g_h);
        cudaGetSymbolAddress((void**)&p_hw, g_hw);
        cudaGetSymbolAddress((void**)&p_wbf, g_Wbf);
        cudaGetSymbolAddress((void**)&p_pool, g_pool);
        cudaGetSymbolAddress((void**)&p_m1, g_m1);
        cudaGetSymbolAddress((void**)&p_m2, g_m2);
    }

    int gemm_grid = (N + 127) / 128;
    int gather_grid = (N + 7) / 8;
    for (int l = 0; l < n_layers; l++) {
        const float* hin = (l == 0) ? x : p_h;
        const __nv_bfloat16* whi = p_wbf + (long long)l * 2 * DD * DD;
        const __nv_bfloat16* wlo = whi + DD * DD;
        gemm_mma_kernel<<<gemm_grid, 256, SM_TOTAL>>>(hin, whi, wlo, p_hw, N);
        gather_kernel<<<gather_grid, 256>>>(p_hw, b_conv + l * DD, p_h, N);
    }

    zero_pool_kernel<<<(G * DD + 255) / 256, 256>>>(G * DD);
    pool_kernel<<<(N * 32 + 255) / 256, 256>>>(batch, N);

    mlp_kernel<<<G, 128>>>(p_pool, W1, b1, p_m1, DD, DD, 1);
    mlp_kernel<<<G, 128>>>(p_m1, W2, b2, p_m2, DD, 64, 1);
    mlp_kernel<<<G, 64>>>(p_m2, W3, b3, (float*)d_out, 64, 10, 0);
}